// round 2
// baseline (speedup 1.0000x reference)
#include <cuda_runtime.h>
#include <math_constants.h>

#define NROWS 8192
#define IN_DIM 128
#define HID 256
#define SLOPE 0.01f
#define S_CONST 8192.0f

// ---------------- scratch (__device__ globals; no allocs allowed) ----------
__device__ float g_Z[NROWS * HID];        // X @ W^T            (8 MB)
__device__ float g_H[NROWS * HID];        // exp(leakyrelu(s*(Z+b)))  (8 MB)
__device__ float g_Ppart[128 * 32 * HID]; // split-K partials of E[0:32] @ H (4 MB)
__device__ float g_v[NROWS];              // normalized first-32-rows of Ep, flattened
__device__ float g_Upart[64 * HID];       // split partials of sum_j v_j Z[j,:]
__device__ float g_w[HID];                // (v^T Z)/S
__device__ float g_s;                     // sum(Ai)+sum(Aj)

// ---------------- kernel 0: scalar s --------------------------------------
__global__ void k_scalar(const float* __restrict__ Ai, const float* __restrict__ Aj) {
    __shared__ float sm[128];
    int t = threadIdx.x;
    sm[t] = Ai[t] + Aj[t];
    __syncthreads();
    for (int o = 64; o > 0; o >>= 1) {
        if (t < o) sm[t] += sm[t + o];
        __syncthreads();
    }
    if (t == 0) g_s = sm[0];
}

// ---------------- kernel A: Z = X@W^T, H = exp(lrelu(s*(Z+b))) -------------
// block: 256 threads (one output column each), 32 rows per block
__global__ void k_zh(const float* __restrict__ X, const float* __restrict__ W,
                     const float* __restrict__ b) {
    __shared__ float4 Xs[32][32];   // 32 rows x 128 floats
    const int c  = threadIdx.x;
    const int r0 = blockIdx.x * 32;

    const float4* X4 = (const float4*)(X + (size_t)r0 * IN_DIM);
    for (int i = c; i < 32 * 32; i += 256)
        ((float4*)Xs)[i] = X4[i];
    __syncthreads();

    const float  s  = g_s;
    const float  bc = b[c];
    const float4* W4 = (const float4*)(W + (size_t)c * IN_DIM);

    float acc[32];
#pragma unroll
    for (int r = 0; r < 32; r++) acc[r] = 0.f;

#pragma unroll
    for (int k4 = 0; k4 < 32; k4++) {
        float4 wv = W4[k4];
#pragma unroll
        for (int r = 0; r < 32; r++) {
            float4 xv = Xs[r][k4];
            acc[r] += xv.x * wv.x + xv.y * wv.y + xv.z * wv.z + xv.w * wv.w;
        }
    }

#pragma unroll
    for (int r = 0; r < 32; r++) {
        float z = acc[r];
        size_t idx = (size_t)(r0 + r) * HID + c;
        g_Z[idx] = z;
        float a  = (z + bc) * s;
        float lr = a > 0.f ? a : SLOPE * a;
        g_H[idx] = __expf(lr);
    }
}

// ---------------- kernel B: split-K partials of P = E[0:32,:] @ H ----------
// grid 128 blocks; block kb handles k in [kb*64, kb*64+64)
__global__ void k_ep(const float* __restrict__ E) {
    __shared__ float Es[64][32];    // [kk][r] so the r-loop reads broadcast float4s
    const int c  = threadIdx.x;
    const int kb = blockIdx.x;
    const int k0 = kb * 64;

    for (int i = c; i < 64 * 32; i += 256) {
        int r = i & 31, kk = i >> 5;
        Es[kk][r] = E[(size_t)r * NROWS + k0 + kk];
    }
    __syncthreads();

    float acc[32];
#pragma unroll
    for (int r = 0; r < 32; r++) acc[r] = 0.f;

    for (int kk = 0; kk < 64; kk++) {
        float h = g_H[(size_t)(k0 + kk) * HID + c];
        const float4* es4 = (const float4*)Es[kk];
#pragma unroll
        for (int r4 = 0; r4 < 8; r4++) {
            float4 e = es4[r4];
            acc[r4 * 4 + 0] += e.x * h;
            acc[r4 * 4 + 1] += e.y * h;
            acc[r4 * 4 + 2] += e.z * h;
            acc[r4 * 4 + 3] += e.w * h;
        }
    }
#pragma unroll
    for (int r = 0; r < 32; r++)
        g_Ppart[(size_t)kb * 32 * HID + r * HID + c] = acc[r];
}

// ---------------- kernel C: reduce partials, row-normalize -> v ------------
// grid 32 blocks (one row of P), 256 threads
__global__ void k_v() {
    const int r = blockIdx.x;
    const int c = threadIdx.x;
    float p = 0.f;
    for (int kb = 0; kb < 128; kb++)
        p += g_Ppart[(size_t)kb * 32 * HID + r * HID + c];

    __shared__ float sm[256];
    sm[c] = p;
    __syncthreads();
    for (int o = 128; o > 0; o >>= 1) {
        if (c < o) sm[c] += sm[c + o];
        __syncthreads();
    }
    g_v[r * HID + c] = p / sm[0];
}

// ---------------- kernel D: partials of u0 = sum_j v_j * Z[j,:] ------------
// grid 64 blocks; block jb handles 128 rows
__global__ void k_u() {
    const int c  = threadIdx.x;
    const int j0 = blockIdx.x * 128;
    float acc = 0.f;
    for (int j = 0; j < 128; j++)
        acc += g_v[j0 + j] * g_Z[(size_t)(j0 + j) * HID + c];
    g_Upart[blockIdx.x * HID + c] = acc;
}

// ---------------- kernel D2: finalize w = u0/S -----------------------------
__global__ void k_w() {
    const int c = threadIdx.x;
    float acc = 0.f;
    for (int jb = 0; jb < 64; jb++) acc += g_Upart[jb * HID + c];
    g_w[c] = acc * (1.0f / S_CONST);
}

// ---------------- kernel E: out[i,:] = softmax(v_i*w + b) ------------------
// one warp per row; 8 warps/block; grid 1024
__global__ void k_out(const float* __restrict__ b, float* __restrict__ out) {
    const int lane = threadIdx.x & 31;
    const int i    = blockIdx.x * 8 + (threadIdx.x >> 5);
    const float vi = g_v[i];

    float l[8];
    float m = -CUDART_INF_F;
#pragma unroll
    for (int t = 0; t < 8; t++) {
        int c = lane + 32 * t;
        l[t] = vi * g_w[c] + b[c];
        m = fmaxf(m, l[t]);
    }
#pragma unroll
    for (int o = 16; o > 0; o >>= 1) m = fmaxf(m, __shfl_xor_sync(0xffffffffu, m, o));

    float s = 0.f;
#pragma unroll
    for (int t = 0; t < 8; t++) { l[t] = __expf(l[t] - m); s += l[t]; }
#pragma unroll
    for (int o = 16; o > 0; o >>= 1) s += __shfl_xor_sync(0xffffffffu, s, o);

    const float inv = 1.0f / s;
#pragma unroll
    for (int t = 0; t < 8; t++)
        out[(size_t)i * HID + lane + 32 * t] = l[t] * inv;
}

// ---------------- kernel F: alpha = outer(v,v)/S  (the 256MB write) --------
// one block per row, 256 threads write float4s
__global__ void k_alpha(float* __restrict__ alpha) {
    const int i = blockIdx.x;
    const float a = g_v[i] * (1.0f / S_CONST);
    const float4* v4 = (const float4*)g_v;
    float4* o4 = (float4*)(alpha + (size_t)i * NROWS);
#pragma unroll
    for (int t = threadIdx.x; t < NROWS / 4; t += 256) {
        float4 vj = v4[t];
        o4[t] = make_float4(a * vj.x, a * vj.y, a * vj.z, a * vj.w);
    }
}

// ---------------- launch ---------------------------------------------------
extern "C" void kernel_launch(void* const* d_in, const int* in_sizes, int n_in,
                              void* d_out, int out_size) {
    const float* X  = (const float*)d_in[0];
    const float* E  = (const float*)d_in[1];
    const float* W  = (const float*)d_in[2];
    const float* b  = (const float*)d_in[3];
    const float* Ai = (const float*)d_in[4];
    const float* Aj = (const float*)d_in[5];

    float* out   = (float*)d_out;                       // (8192, 256)
    float* alpha = out + (size_t)NROWS * HID;           // (8192, 8192)

    k_scalar<<<1, 128>>>(Ai, Aj);
    k_zh<<<NROWS / 32, 256>>>(X, W, b);
    k_ep<<<128, 256>>>(E);
    k_v<<<32, 256>>>();
    k_u<<<64, 256>>>();
    k_w<<<1, 256>>>();
    k_out<<<NROWS / 8, 256>>>(b, out);
    k_alpha<<<NROWS, 256>>>(alpha);
}

// round 3
// speedup vs baseline: 1.2672x; 1.2672x over previous
#include <cuda_runtime.h>
#include <math_constants.h>

#define NROWS 8192
#define IN_DIM 128
#define HID 256
#define SLOPE 0.01f
#define S_CONST 8192.0f

// ---------------- scratch (__device__ globals; no allocs allowed) ----------
__device__ __align__(16) float g_H[NROWS * HID];         // exp(lrelu(s*(XW^T+b)))  (8 MB)
__device__ __align__(16) float g_Ppart[32 * 128 * HID];  // [r][kb][c] split-K partials (4 MB)
__device__ __align__(16) float g_v[NROWS];               // normalized flat[:8192]
__device__ __align__(16) float g_Upart[32 * IN_DIM];     // per-v-row partials of v^T X
__device__ __align__(16) float g_w[HID];                 // ((v^T X) W^T)/S

// ---------------- kernel A: H = exp(lrelu(s*(X@W^T + b))) ------------------
// grid 128 blocks (64 rows each), 256 threads (one output column each)
__global__ void k_zh(const float* __restrict__ X, const float* __restrict__ W,
                     const float* __restrict__ b,
                     const float* __restrict__ Ai, const float* __restrict__ Aj) {
    __shared__ float4 Xs[64][32];   // 64 rows x 128 floats, [row][k4]
    __shared__ float sred[128];
    const int c  = threadIdx.x;
    const int r0 = blockIdx.x * 64;

    if (c < 128) sred[c] = Ai[c] + Aj[c];

    const float4* X4 = (const float4*)(X + (size_t)r0 * IN_DIM);
    for (int i = c; i < 64 * 32; i += 256)
        ((float4*)Xs)[i] = X4[i];
    __syncthreads();

    // finish s-reduction
    if (c < 64) sred[c] += sred[c + 64];
    __syncthreads();
    if (c < 32) {
        float x = sred[c] + sred[c + 32];
#pragma unroll
        for (int o = 16; o > 0; o >>= 1) x += __shfl_xor_sync(0xffffffffu, x, o);
        if (c == 0) sred[0] = x;
    }
    __syncthreads();
    const float s  = sred[0];
    const float bc = b[c];

    float acc[64];
#pragma unroll
    for (int r = 0; r < 64; r++) acc[r] = 0.f;

    const float4* W4 = (const float4*)(W + (size_t)c * IN_DIM);
#pragma unroll 1
    for (int k4 = 0; k4 < 32; k4++) {
        float4 wv = W4[k4];
#pragma unroll
        for (int r = 0; r < 64; r++) {
            float4 xv = Xs[r][k4];                        // broadcast LDS.128
            acc[r] += xv.x * wv.x + xv.y * wv.y + xv.z * wv.z + xv.w * wv.w;
        }
    }

#pragma unroll
    for (int r = 0; r < 64; r++) {
        float a  = (acc[r] + bc) * s;
        float lr = a > 0.f ? a : SLOPE * a;
        g_H[(size_t)(r0 + r) * HID + c] = __expf(lr);
    }
}

// ---------------- kernel B: split-K partials of P = E[0:32,:] @ H ----------
// grid 128 blocks; block kb handles k in [kb*64, kb*64+64)
__global__ void k_ep(const float* __restrict__ E) {
    __shared__ __align__(16) float Es[64][32];   // [kk][r]: broadcast float4 reads
    const int c  = threadIdx.x;
    const int kb = blockIdx.x;
    const int k0 = kb * 64;

    for (int i = c; i < 64 * 32; i += 256) {
        int r = i & 31, kk = i >> 5;
        Es[kk][r] = E[(size_t)r * NROWS + k0 + kk];
    }
    __syncthreads();

    float acc[32];
#pragma unroll
    for (int r = 0; r < 32; r++) acc[r] = 0.f;

#pragma unroll 4
    for (int kk = 0; kk < 64; kk++) {
        float h = g_H[(size_t)(k0 + kk) * HID + c];
        const float4* es4 = (const float4*)Es[kk];
#pragma unroll
        for (int r4 = 0; r4 < 8; r4++) {
            float4 e = es4[r4];
            acc[r4 * 4 + 0] += e.x * h;
            acc[r4 * 4 + 1] += e.y * h;
            acc[r4 * 4 + 2] += e.z * h;
            acc[r4 * 4 + 3] += e.w * h;
        }
    }
#pragma unroll
    for (int r = 0; r < 32; r++)
        g_Ppart[((size_t)r * 128 + kb) * HID + c] = acc[r];
}

// ---------------- kernel C: reduce partials -> v; also partial of v^T X ----
// grid 32 blocks (one v-row each), 1024 threads
__global__ void k_v(const float* __restrict__ X) {
    __shared__ float sm[16][256];
    __shared__ float red[256];
    __shared__ float vsm[256];
    __shared__ float su[8][128];
    const int t = threadIdx.x;
    const int r = blockIdx.x;

    {   // phase 1: sum 128 kb-partials (contiguous, float4)
        const float4* P4 = (const float4*)(g_Ppart + (size_t)r * 128 * HID);
        const int c4 = t & 63, y = t >> 6;
        float4 a = make_float4(0.f, 0.f, 0.f, 0.f);
#pragma unroll
        for (int m = 0; m < 8; m++) {
            float4 p = P4[(size_t)(y + 16 * m) * 64 + c4];
            a.x += p.x; a.y += p.y; a.z += p.z; a.w += p.w;
        }
        sm[y][c4 * 4 + 0] = a.x;
        sm[y][c4 * 4 + 1] = a.y;
        sm[y][c4 * 4 + 2] = a.z;
        sm[y][c4 * 4 + 3] = a.w;
    }
    __syncthreads();

    float p = 0.f;
    if (t < 256) {
#pragma unroll
        for (int y = 0; y < 16; y++) p += sm[y][t];
        red[t] = p;
    }
    __syncthreads();
    if (t < 128) red[t] += red[t + 128];
    __syncthreads();
    if (t < 64)  red[t] += red[t + 64];
    __syncthreads();
    if (t < 32) {
        float x = red[t] + red[t + 32];
#pragma unroll
        for (int o = 16; o > 0; o >>= 1) x += __shfl_xor_sync(0xffffffffu, x, o);
        if (t == 0) red[0] = x;
    }
    __syncthreads();
    const float inv = 1.0f / red[0];
    if (t < 256) {
        float v = p * inv;
        vsm[t] = v;
        g_v[r * HID + t] = v;
    }
    __syncthreads();

    {   // phase 2: partial t_r[k] = sum_{c<256} v_c * X[256r + c][k]
        const int k = t & 127, jg = t >> 7;     // jg in [0,8)
        float acc = 0.f;
        const float* Xr = X + ((size_t)r * 256 + jg * 32) * IN_DIM + k;
#pragma unroll
        for (int jj = 0; jj < 32; jj++)
            acc += vsm[jg * 32 + jj] * Xr[(size_t)jj * IN_DIM];
        su[jg][k] = acc;
    }
    __syncthreads();
    if (t < 128) {
        float tot = 0.f;
#pragma unroll
        for (int g = 0; g < 8; g++) tot += su[g][t];
        g_Upart[r * IN_DIM + t] = tot;
    }
}

// ---------------- kernel D: w = ((v^T X) @ W^T)/S --------------------------
// grid 32 blocks, 256 threads; warp w handles column c = bid*8 + w
__global__ void k_w(const float* __restrict__ W) {
    __shared__ __align__(16) float ts[128];
    const int t = threadIdx.x;
    if (t < 128) {
        float a = 0.f;
#pragma unroll
        for (int r = 0; r < 32; r++) a += g_Upart[r * IN_DIM + t];
        ts[t] = a;
    }
    __syncthreads();
    const int wrp = t >> 5, l = t & 31;
    const int c = blockIdx.x * 8 + wrp;
    float4 wv = ((const float4*)(W + (size_t)c * IN_DIM))[l];
    float4 tv = ((const float4*)ts)[l];
    float d = wv.x * tv.x + wv.y * tv.y + wv.z * tv.z + wv.w * tv.w;
#pragma unroll
    for (int o = 16; o > 0; o >>= 1) d += __shfl_xor_sync(0xffffffffu, d, o);
    if (l == 0) g_w[c] = d * (1.0f / S_CONST);
}

// ---------------- kernel E: alpha row + fused out softmax ------------------
// one block per row i, 256 threads
__global__ void k_alpha(const float* __restrict__ b, float* __restrict__ out,
                        float* __restrict__ alpha) {
    __shared__ float red[256];
    const int t = threadIdx.x;
    const int i = blockIdx.x;
    const float vi = g_v[i];

    // ---- out[i,:] = softmax(vi * w + b) ----
    float l = vi * g_w[t] + b[t];
    red[t] = l;
    __syncthreads();
    if (t < 128) red[t] = fmaxf(red[t], red[t + 128]);
    __syncthreads();
    if (t < 64)  red[t] = fmaxf(red[t], red[t + 64]);
    __syncthreads();
    if (t < 32) {
        float x = fmaxf(red[t], red[t + 32]);
#pragma unroll
        for (int o = 16; o > 0; o >>= 1) x = fmaxf(x, __shfl_xor_sync(0xffffffffu, x, o));
        if (t == 0) red[0] = x;
    }
    __syncthreads();
    const float m = red[0];
    __syncthreads();
    float e = __expf(l - m);
    red[t] = e;
    __syncthreads();
    if (t < 128) red[t] += red[t + 128];
    __syncthreads();
    if (t < 64)  red[t] += red[t + 64];
    __syncthreads();
    if (t < 32) {
        float x = red[t] + red[t + 32];
#pragma unroll
        for (int o = 16; o > 0; o >>= 1) x += __shfl_xor_sync(0xffffffffu, x, o);
        if (t == 0) red[0] = x;
    }
    __syncthreads();
    out[(size_t)i * HID + t] = e * (1.0f / red[0]);

    // ---- alpha[i,:] = (vi/S) * v ----
    const float a = vi * (1.0f / S_CONST);
    const float4* v4 = (const float4*)g_v;
    float4* o4 = (float4*)(alpha + (size_t)i * NROWS);
#pragma unroll
    for (int it = 0; it < 8; it++) {
        float4 vv = v4[t + 256 * it];
        o4[t + 256 * it] = make_float4(a * vv.x, a * vv.y, a * vv.z, a * vv.w);
    }
}

// ---------------- launch ---------------------------------------------------
extern "C" void kernel_launch(void* const* d_in, const int* in_sizes, int n_in,
                              void* d_out, int out_size) {
    const float* X  = (const float*)d_in[0];
    const float* E  = (const float*)d_in[1];
    const float* W  = (const float*)d_in[2];
    const float* b  = (const float*)d_in[3];
    const float* Ai = (const float*)d_in[4];
    const float* Aj = (const float*)d_in[5];

    float* out   = (float*)d_out;                       // (8192, 256)
    float* alpha = out + (size_t)NROWS * HID;           // (8192, 8192)

    k_zh   <<<128, 256>>>(X, W, b, Ai, Aj);
    k_ep   <<<128, 256>>>(E);
    k_v    <<<32, 1024>>>(X);
    k_w    <<<32, 256>>>(W);
    k_alpha<<<NROWS, 256>>>(b, out, alpha);
}